// round 4
// baseline (speedup 1.0000x reference)
#include <cuda_runtime.h>
#include <math.h>

#define B_ 64
#define L_ 512
#define E_ 512
#define C_ 32
#define U_ 8
#define K_ 9
#define S_ 256

// ---------------- scratch (device globals; no allocation) ----------------
__device__ float g_h[(size_t)B_ * L_ * C_];            // 4 MB   conv1 output [B,L,C]
__device__ float g_p[(size_t)B_ * U_ * S_ * C_];       // 16 MB  squashed primary caps [B,U,S,C]
__device__ float g_uh[(size_t)B_ * U_ * K_ * S_ * C_]; // 151 MB u_hat [B,U,K,S,C]
__device__ float g_c1wT[E_ * 9 * C_];                  // conv1 weights transposed [e][t][co]
__device__ float g_pwT[C_ * 9 * U_ * C_];              // prim weights transposed [ci][t][uc]
__device__ float g_logA[B_ * U_ * K_];                 // routing logits ping
__device__ float g_logB[B_ * U_ * K_];                 // routing logits pong

// ---------------- weight transposes ----------------
__global__ void k_prep(const float* __restrict__ c1w, const float* __restrict__ pw) {
    int i = blockIdx.x * 256 + threadIdx.x;
    if (i < E_ * 9 * C_) {
        int e = i / (9 * C_), t = (i / C_) % 9, co = i % C_;
        g_c1wT[i] = c1w[(co * E_ + e) * 9 + t];
    } else {
        int j = i - E_ * 9 * C_;
        if (j < C_ * 9 * 256) {
            int ci = j / (9 * 256), t = (j / 256) % 9, uc = j % 256;
            g_pwT[j] = pw[(uc * C_ + ci) * 9 + t];
        }
    }
}

// ---------------- conv1 (fused embedding gather): E=512 -> C=32, k=9, pad 4, ReLU ----
// Grid (L/128, B), 128 threads. Thread tile: 8 co x 4 l. K-loop = 512 e x 9 t.
// Input rows are gathered straight from the embedding table (token ids cached in smem).
__global__ void __launch_bounds__(128) k_conv1(const int* __restrict__ x,
                                               const float* __restrict__ mask,
                                               const float* __restrict__ emb,
                                               const float* __restrict__ bias) {
    __shared__ float esm[16 * 136];       // [e_local][row], rows = 128 + 8
    __shared__ float wsm[16 * 9 * 32];    // [e_local][t][co]
    __shared__ int   tsm[136];            // token id per row (l = lbase-4+row), -1 if OOB
    __shared__ float msm[136];            // mask per row
    int b = blockIdx.y;
    int lbase = blockIdx.x * 128;
    int tid = threadIdx.x, warp = tid >> 5, lane = tid & 31;
    int l0 = lane * 4;

    for (int row = tid; row < 136; row += 128) {
        int l = lbase - 4 + row;
        if (l >= 0 && l < L_) {
            tsm[row] = x[b * L_ + l];
            msm[row] = mask[b * L_ + l];
        } else {
            tsm[row] = -1;
            msm[row] = 0.f;
        }
    }

    float acc[8][4];
#pragma unroll
    for (int i = 0; i < 8; i++)
#pragma unroll
        for (int j = 0; j < 4; j++) acc[i][j] = 0.f;

    __syncthreads();

    for (int ch = 0; ch < 32; ch++) {
        int ec = ch * 16;
        if (ch) __syncthreads();
        // gather e window straight from emb (transposed into [e][row])
        for (int idx = tid; idx < 136 * 4; idx += 128) {
            int row = idx >> 2, q = idx & 3;
            int tok = tsm[row];
            float4 v = make_float4(0.f, 0.f, 0.f, 0.f);
            if (tok >= 0) {
                v = *(const float4*)(emb + (size_t)tok * E_ + ec + q * 4);
                float m = msm[row];
                v.x *= m; v.y *= m; v.z *= m; v.w *= m;
            }
            esm[(q * 4 + 0) * 136 + row] = v.x;
            esm[(q * 4 + 1) * 136 + row] = v.y;
            esm[(q * 4 + 2) * 136 + row] = v.z;
            esm[(q * 4 + 3) * 136 + row] = v.w;
        }
        // load weights chunk (already [e][t][co] in global)
        {
            const float4* src = (const float4*)(g_c1wT + ec * 288);
            float4* dst = (float4*)wsm;
            for (int idx = tid; idx < 1152; idx += 128) dst[idx] = src[idx];
        }
        __syncthreads();
#pragma unroll 1
        for (int el = 0; el < 16; el++) {
            float ev[12];
            const float4* er = (const float4*)(esm + el * 136 + l0);
#pragma unroll
            for (int q = 0; q < 3; q++) {
                float4 v = er[q];
                ev[q * 4 + 0] = v.x; ev[q * 4 + 1] = v.y;
                ev[q * 4 + 2] = v.z; ev[q * 4 + 3] = v.w;
            }
#pragma unroll
            for (int t = 0; t < 9; t++) {
                const float* wp = wsm + (el * 9 + t) * 32 + warp * 8;
                float4 wa = *(const float4*)wp;
                float4 wb = *(const float4*)(wp + 4);
                float wv[8] = {wa.x, wa.y, wa.z, wa.w, wb.x, wb.y, wb.z, wb.w};
#pragma unroll
                for (int j = 0; j < 4; j++) {
                    float e = ev[j + t];
#pragma unroll
                    for (int i = 0; i < 8; i++) acc[i][j] = fmaf(wv[i], e, acc[i][j]);
                }
            }
        }
    }
    float bi[8];
#pragma unroll
    for (int i = 0; i < 8; i++) bi[i] = bias[warp * 8 + i];
#pragma unroll
    for (int j = 0; j < 4; j++) {
        int l = lbase + l0 + j;
        float4 o0, o1;
        o0.x = fmaxf(acc[0][j] + bi[0], 0.f);
        o0.y = fmaxf(acc[1][j] + bi[1], 0.f);
        o0.z = fmaxf(acc[2][j] + bi[2], 0.f);
        o0.w = fmaxf(acc[3][j] + bi[3], 0.f);
        o1.x = fmaxf(acc[4][j] + bi[4], 0.f);
        o1.y = fmaxf(acc[5][j] + bi[5], 0.f);
        o1.z = fmaxf(acc[6][j] + bi[6], 0.f);
        o1.w = fmaxf(acc[7][j] + bi[7], 0.f);
        float* dst = g_h + ((size_t)(b * L_ + l)) * C_ + warp * 8;
        *(float4*)dst = o0;
        *(float4*)(dst + 4) = o1;
    }
}

// ---------------- primary caps conv: 32 -> 256, k=9, pad 4, stride 2, + squash ----------------
// Grid (S/32, B), 256 threads. Thread tile: 8 uc x 4 s.
__global__ void __launch_bounds__(256) k_prim(const float* __restrict__ bias) {
    __shared__ float sbuf[9504];          // hsm(288) + wsm(9216); reused as psm(8224)
    int b = blockIdx.y;
    int sb = blockIdx.x * 32;
    int tid = threadIdx.x;
    int ucg = tid >> 3, sg = tid & 7;
    float acc[8][4];
#pragma unroll
    for (int i = 0; i < 8; i++)
#pragma unroll
        for (int j = 0; j < 4; j++) acc[i][j] = 0.f;

    float* hsm = sbuf;          // [4 ci][72 rows]
    float* wsm = sbuf + 288;    // [4 ci][9 t][256 uc]
    int lorg = 2 * sb - 4;

    for (int ch = 0; ch < 8; ch++) {
        int ci0 = ch * 4;
        __syncthreads();
        for (int row = tid; row < 72; row += 256) {
            int l = lorg + row;
            float4 v = make_float4(0.f, 0.f, 0.f, 0.f);
            if (l >= 0 && l < L_)
                v = *(const float4*)(g_h + ((size_t)(b * L_ + l)) * C_ + ci0);
            hsm[row] = v.x;
            hsm[72 + row] = v.y;
            hsm[144 + row] = v.z;
            hsm[216 + row] = v.w;
        }
        {
            const float4* src = (const float4*)(g_pwT + ci0 * 2304);
            float4* dst = (float4*)wsm;
            for (int idx = tid; idx < 2304; idx += 256) dst[idx] = src[idx];
        }
        __syncthreads();
#pragma unroll
        for (int cl = 0; cl < 4; cl++) {
            float hv[16];
            const float4* hr = (const float4*)(hsm + cl * 72 + sg * 8);
#pragma unroll
            for (int q = 0; q < 4; q++) {
                float4 v = hr[q];
                hv[q * 4 + 0] = v.x; hv[q * 4 + 1] = v.y;
                hv[q * 4 + 2] = v.z; hv[q * 4 + 3] = v.w;
            }
#pragma unroll
            for (int t = 0; t < 9; t++) {
                const float* wp = wsm + (cl * 9 + t) * 256 + ucg * 8;
                float4 wa = *(const float4*)wp;
                float4 wb = *(const float4*)(wp + 4);
                float wv[8] = {wa.x, wa.y, wa.z, wa.w, wb.x, wb.y, wb.z, wb.w};
#pragma unroll
                for (int j = 0; j < 4; j++) {
                    float h = hv[2 * j + t];
#pragma unroll
                    for (int i = 0; i < 8; i++) acc[i][j] = fmaf(wv[i], h, acc[i][j]);
                }
            }
        }
    }
    __syncthreads();
    // write raw primary caps into smem for the squash regroup (rows padded to 257 for bank spread)
    float* psm = sbuf;
    float bi[8];
#pragma unroll
    for (int i = 0; i < 8; i++) bi[i] = bias[ucg * 8 + i];
#pragma unroll
    for (int j = 0; j < 4; j++)
#pragma unroll
        for (int i = 0; i < 8; i++)
            psm[(sg * 4 + j) * 257 + ucg * 8 + i] = acc[i][j] + bi[i];
    __syncthreads();
    // squash per (u, s) over c=32
    int u = tid >> 5, sl = tid & 31;
    const float* pr = psm + sl * 257 + u * 32;
    float sq = 0.f;
#pragma unroll
    for (int c = 0; c < 32; c++) { float pv = pr[c]; sq += pv * pv; }
    float sc = (sq / (1.f + sq)) * rsqrtf(sq + 1e-8f);
    float* dst = g_p + (((size_t)(b * U_ + u)) * S_ + sb + sl) * C_;
#pragma unroll
    for (int c = 0; c < 32; c++) dst[c] = pr[c] * sc;
}

// ---------------- u_hat[b,u,k,s,:] = p[b,u,s,:] @ W[u,k] ----------------
// Grid (K, U, B), 128 threads; each thread does rows s = tid and tid+128.
__global__ void __launch_bounds__(128) k_uhat(const float* __restrict__ W) {
    __shared__ float wsm[1024];   // W[u,k] 32x32
    int k = blockIdx.x, u = blockIdx.y, b = blockIdx.z;
    int tid = threadIdx.x;
    const float* Wk = W + (size_t)(u * K_ + k) * 1024;
    for (int i = tid; i < 256; i += 128) ((float4*)wsm)[i] = ((const float4*)Wk)[i];
    __syncthreads();

    float4 a0[8], a1[8];
#pragma unroll
    for (int q = 0; q < 8; q++) { a0[q] = make_float4(0.f, 0.f, 0.f, 0.f); a1[q] = a0[q]; }
    const float4* p0 = (const float4*)(g_p + (((size_t)(b * U_ + u)) * S_ + tid) * C_);
    const float4* p1 = (const float4*)(g_p + (((size_t)(b * U_ + u)) * S_ + tid + 128) * C_);
#pragma unroll 1
    for (int c4 = 0; c4 < 8; c4++) {
        float4 pa = p0[c4], pb = p1[c4];
        float pav[4] = {pa.x, pa.y, pa.z, pa.w};
        float pbv[4] = {pb.x, pb.y, pb.z, pb.w};
#pragma unroll
        for (int cc = 0; cc < 4; cc++) {
            float xa = pav[cc], xb = pbv[cc];
            const float4* wr = (const float4*)(wsm + (c4 * 4 + cc) * 32);
#pragma unroll
            for (int q = 0; q < 8; q++) {
                float4 wv = wr[q];
                a0[q].x = fmaf(xa, wv.x, a0[q].x); a0[q].y = fmaf(xa, wv.y, a0[q].y);
                a0[q].z = fmaf(xa, wv.z, a0[q].z); a0[q].w = fmaf(xa, wv.w, a0[q].w);
                a1[q].x = fmaf(xb, wv.x, a1[q].x); a1[q].y = fmaf(xb, wv.y, a1[q].y);
                a1[q].z = fmaf(xb, wv.z, a1[q].z); a1[q].w = fmaf(xb, wv.w, a1[q].w);
            }
        }
    }
    float4* d0 = (float4*)(g_uh + ((size_t)(((b * U_ + u) * K_ + k) * S_ + tid)) * C_);
    float4* d1 = (float4*)(g_uh + ((size_t)(((b * U_ + u) * K_ + k) * S_ + tid + 128)) * C_);
#pragma unroll
    for (int q = 0; q < 8; q++) { d0[q] = a0[q]; d1[q] = a1[q]; }
}

// ---------------- routing iteration ----------------
// Logits are constant over S (agree is broadcast over S), so c is per-(b,u,k).
// PHASE 0: c uniform, writes logA = agree.
// PHASE 1: c = softmax(logA), writes logB = logA + agree.
// PHASE 2: c = softmax(logB), reduces mean_s(v) -> out.
template <int PHASE>
__global__ void __launch_bounds__(256) k_route(float* __restrict__ out) {
    __shared__ float cs[8];
    __shared__ float sbuf[8448];
    int k = blockIdx.x, b = blockIdx.y, s = threadIdx.x;

    if (PHASE == 0) {
        if (s < 8) cs[s] = 1.f / 9.f;
    } else {
        const float* lin = (PHASE == 1) ? g_logA : g_logB;
        if (s < 8) {
            const float* lp = lin + (b * U_ + s) * K_;
            float lg[9], m = -1e30f;
#pragma unroll
            for (int i = 0; i < 9; i++) { lg[i] = lp[i]; m = fmaxf(m, lg[i]); }
            float sum = 0.f;
#pragma unroll
            for (int i = 0; i < 9; i++) sum += expf(lg[i] - m);
            cs[s] = expf(lg[k] - m) / sum;
        }
    }
    __syncthreads();

    float4 sa[8];
#pragma unroll
    for (int q = 0; q < 8; q++) sa[q] = make_float4(0.f, 0.f, 0.f, 0.f);
#pragma unroll 1
    for (int u = 0; u < 8; u++) {
        float cu = cs[u];
        const float4* up =
            (const float4*)(g_uh + ((size_t)(((b * U_ + u) * K_ + k) * S_ + s)) * C_);
#pragma unroll
        for (int q = 0; q < 8; q++) {
            float4 v = up[q];
            sa[q].x += cu * v.x; sa[q].y += cu * v.y;
            sa[q].z += cu * v.z; sa[q].w += cu * v.w;
        }
    }
    float sq = 0.f;
#pragma unroll
    for (int q = 0; q < 8; q++)
        sq += sa[q].x * sa[q].x + sa[q].y * sa[q].y + sa[q].z * sa[q].z + sa[q].w * sa[q].w;
    float sc = (sq / (1.f + sq)) * rsqrtf(sq + 1e-8f);
    float4 v8[8];
#pragma unroll
    for (int q = 0; q < 8; q++) {
        v8[q].x = sa[q].x * sc; v8[q].y = sa[q].y * sc;
        v8[q].z = sa[q].z * sc; v8[q].w = sa[q].w * sc;
    }

    if (PHASE < 2) {
#pragma unroll 1
        for (int u = 0; u < 8; u++) {
            const float4* up =
                (const float4*)(g_uh + ((size_t)(((b * U_ + u) * K_ + k) * S_ + s)) * C_);
            float d = 0.f;
#pragma unroll
            for (int q = 0; q < 8; q++) {
                float4 w = up[q];
                d += w.x * v8[q].x + w.y * v8[q].y + w.z * v8[q].z + w.w * v8[q].w;
            }
            sbuf[u * 256 + s] = d;
        }
        __syncthreads();
        int warp = s >> 5, lane = s & 31;
        float t = 0.f;
#pragma unroll
        for (int j = 0; j < 8; j++) t += sbuf[warp * 256 + lane + j * 32];
#pragma unroll
        for (int off = 16; off > 0; off >>= 1) t += __shfl_xor_sync(0xffffffffu, t, off);
        if (lane == 0) {
            int li = (b * U_ + warp) * K_ + k;
            if (PHASE == 0) g_logA[li] = t;
            else            g_logB[li] = g_logA[li] + t;
        }
    } else {
        // v8 rows into smem, then parallel column mean.
#pragma unroll
        for (int q = 0; q < 8; q++) {
            sbuf[s * 33 + q * 4 + 0] = v8[q].x;
            sbuf[s * 33 + q * 4 + 1] = v8[q].y;
            sbuf[s * 33 + q * 4 + 2] = v8[q].z;
            sbuf[s * 33 + q * 4 + 3] = v8[q].w;
        }
        __syncthreads();
        int col = s & 31, seg = s >> 5;
        float t = 0.f;
#pragma unroll
        for (int r = 0; r < 32; r++) t += sbuf[(seg * 32 + r) * 33 + col];
        __syncthreads();
        sbuf[seg * 32 + col] = t;
        __syncthreads();
        if (s < 32) {
            float acc = 0.f;
#pragma unroll
            for (int g = 0; g < 8; g++) acc += sbuf[g * 32 + s];
            out[(b * K_ + k) * C_ + s] = acc * (1.f / 256.f);
        }
    }
}

// ---------------- launch ----------------
extern "C" void kernel_launch(void* const* d_in, const int* in_sizes, int n_in,
                              void* d_out, int out_size) {
    const int*   x    = (const int*)d_in[0];
    const float* mask = (const float*)d_in[1];
    const float* emb  = (const float*)d_in[2];
    const float* c1w  = (const float*)d_in[3];
    const float* c1b  = (const float*)d_in[4];
    const float* pw   = (const float*)d_in[5];
    const float* pb   = (const float*)d_in[6];
    const float* W    = (const float*)d_in[7];
    float* out = (float*)d_out;

    k_prep<<<(E_ * 9 * C_ + C_ * 9 * 256 + 255) / 256, 256>>>(c1w, pw);
    k_conv1<<<dim3(L_ / 128, B_), 128>>>(x, mask, emb, c1b);
    k_prim<<<dim3(S_ / 32, B_), 256>>>(pb);
    k_uhat<<<dim3(K_, U_, B_), 128>>>(W);
    k_route<0><<<dim3(K_, B_), 256>>>(out);
    k_route<1><<<dim3(K_, B_), 256>>>(out);
    k_route<2><<<dim3(K_, B_), 256>>>(out);
}

// round 7
// speedup vs baseline: 1.2444x; 1.2444x over previous
#include <cuda_runtime.h>
#include <cuda_bf16.h>
#include <math.h>

#define B_ 64
#define L_ 512
#define E_ 512
#define C_ 32
#define U_ 8
#define K_ 9
#define S_ 256

// ---------------- scratch (device globals; no allocation) ----------------
__device__ float g_h[(size_t)B_ * L_ * C_];            // 4 MB   conv1 output [B,L,C]
__device__ float g_p[(size_t)B_ * U_ * S_ * C_];       // 16 MB  squashed primary caps [B,U,S,C]
__device__ __nv_bfloat16 g_uh[(size_t)B_ * U_ * K_ * S_ * C_]; // 75 MB u_hat bf16 [B,U,K,S,C]
__device__ float g_c1wT[E_ * 9 * C_];                  // conv1 weights transposed [e][t][co]
__device__ float g_pwT[C_ * 9 * U_ * C_];              // prim weights transposed [ci][t][uc]
__device__ float g_logA[B_ * U_ * K_];                 // routing logits ping
__device__ float g_logB[B_ * U_ * K_];                 // routing logits pong

// ---------------- weight transposes ----------------
__global__ void k_prep(const float* __restrict__ c1w, const float* __restrict__ pw) {
    int i = blockIdx.x * 256 + threadIdx.x;
    if (i < E_ * 9 * C_) {
        int e = i / (9 * C_), t = (i / C_) % 9, co = i % C_;
        g_c1wT[i] = c1w[(co * E_ + e) * 9 + t];
    } else {
        int j = i - E_ * 9 * C_;
        if (j < C_ * 9 * 256) {
            int ci = j / (9 * 256), t = (j / 256) % 9, uc = j % 256;
            g_pwT[j] = pw[(uc * C_ + ci) * 9 + t];
        }
    }
}

// ---------------- conv1 (fused embedding gather): E=512 -> C=32, k=9, pad 4, ReLU ----
__global__ void __launch_bounds__(128) k_conv1(const int* __restrict__ x,
                                               const float* __restrict__ mask,
                                               const float* __restrict__ emb,
                                               const float* __restrict__ bias) {
    __shared__ float esm[16 * 136];       // [e_local][row], rows = 128 + 8
    __shared__ float wsm[16 * 9 * 32];    // [e_local][t][co]
    __shared__ int   tsm[136];
    __shared__ float msm[136];
    int b = blockIdx.y;
    int lbase = blockIdx.x * 128;
    int tid = threadIdx.x, warp = tid >> 5, lane = tid & 31;
    int l0 = lane * 4;

    for (int row = tid; row < 136; row += 128) {
        int l = lbase - 4 + row;
        if (l >= 0 && l < L_) {
            tsm[row] = x[b * L_ + l];
            msm[row] = mask[b * L_ + l];
        } else {
            tsm[row] = -1;
            msm[row] = 0.f;
        }
    }

    float acc[8][4];
#pragma unroll
    for (int i = 0; i < 8; i++)
#pragma unroll
        for (int j = 0; j < 4; j++) acc[i][j] = 0.f;

    __syncthreads();

    for (int ch = 0; ch < 32; ch++) {
        int ec = ch * 16;
        if (ch) __syncthreads();
        for (int idx = tid; idx < 136 * 4; idx += 128) {
            int row = idx >> 2, q = idx & 3;
            int tok = tsm[row];
            float4 v = make_float4(0.f, 0.f, 0.f, 0.f);
            if (tok >= 0) {
                v = *(const float4*)(emb + (size_t)tok * E_ + ec + q * 4);
                float m = msm[row];
                v.x *= m; v.y *= m; v.z *= m; v.w *= m;
            }
            esm[(q * 4 + 0) * 136 + row] = v.x;
            esm[(q * 4 + 1) * 136 + row] = v.y;
            esm[(q * 4 + 2) * 136 + row] = v.z;
            esm[(q * 4 + 3) * 136 + row] = v.w;
        }
        {
            const float4* src = (const float4*)(g_c1wT + ec * 288);
            float4* dst = (float4*)wsm;
            for (int idx = tid; idx < 1152; idx += 128) dst[idx] = src[idx];
        }
        __syncthreads();
#pragma unroll 1
        for (int el = 0; el < 16; el++) {
            float ev[12];
            const float4* er = (const float4*)(esm + el * 136 + l0);
#pragma unroll
            for (int q = 0; q < 3; q++) {
                float4 v = er[q];
                ev[q * 4 + 0] = v.x; ev[q * 4 + 1] = v.y;
                ev[q * 4 + 2] = v.z; ev[q * 4 + 3] = v.w;
            }
#pragma unroll
            for (int t = 0; t < 9; t++) {
                const float* wp = wsm + (el * 9 + t) * 32 + warp * 8;
                float4 wa = *(const float4*)wp;
                float4 wb = *(const float4*)(wp + 4);
                float wv[8] = {wa.x, wa.y, wa.z, wa.w, wb.x, wb.y, wb.z, wb.w};
#pragma unroll
                for (int j = 0; j < 4; j++) {
                    float e = ev[j + t];
#pragma unroll
                    for (int i = 0; i < 8; i++) acc[i][j] = fmaf(wv[i], e, acc[i][j]);
                }
            }
        }
    }
    float bi[8];
#pragma unroll
    for (int i = 0; i < 8; i++) bi[i] = bias[warp * 8 + i];
#pragma unroll
    for (int j = 0; j < 4; j++) {
        int l = lbase + l0 + j;
        float4 o0, o1;
        o0.x = fmaxf(acc[0][j] + bi[0], 0.f);
        o0.y = fmaxf(acc[1][j] + bi[1], 0.f);
        o0.z = fmaxf(acc[2][j] + bi[2], 0.f);
        o0.w = fmaxf(acc[3][j] + bi[3], 0.f);
        o1.x = fmaxf(acc[4][j] + bi[4], 0.f);
        o1.y = fmaxf(acc[5][j] + bi[5], 0.f);
        o1.z = fmaxf(acc[6][j] + bi[6], 0.f);
        o1.w = fmaxf(acc[7][j] + bi[7], 0.f);
        float* dst = g_h + ((size_t)(b * L_ + l)) * C_ + warp * 8;
        *(float4*)dst = o0;
        *(float4*)(dst + 4) = o1;
    }
}

// ---------------- primary caps conv: 32 -> 256, k=9, pad 4, stride 2, + squash ----------------
__global__ void __launch_bounds__(256) k_prim(const float* __restrict__ bias) {
    __shared__ float sbuf[9504];
    int b = blockIdx.y;
    int sb = blockIdx.x * 32;
    int tid = threadIdx.x;
    int ucg = tid >> 3, sg = tid & 7;
    float acc[8][4];
#pragma unroll
    for (int i = 0; i < 8; i++)
#pragma unroll
        for (int j = 0; j < 4; j++) acc[i][j] = 0.f;

    float* hsm = sbuf;
    float* wsm = sbuf + 288;
    int lorg = 2 * sb - 4;

    for (int ch = 0; ch < 8; ch++) {
        int ci0 = ch * 4;
        __syncthreads();
        for (int row = tid; row < 72; row += 256) {
            int l = lorg + row;
            float4 v = make_float4(0.f, 0.f, 0.f, 0.f);
            if (l >= 0 && l < L_)
                v = *(const float4*)(g_h + ((size_t)(b * L_ + l)) * C_ + ci0);
            hsm[row] = v.x;
            hsm[72 + row] = v.y;
            hsm[144 + row] = v.z;
            hsm[216 + row] = v.w;
        }
        {
            const float4* src = (const float4*)(g_pwT + ci0 * 2304);
            float4* dst = (float4*)wsm;
            for (int idx = tid; idx < 2304; idx += 256) dst[idx] = src[idx];
        }
        __syncthreads();
#pragma unroll
        for (int cl = 0; cl < 4; cl++) {
            float hv[16];
            const float4* hr = (const float4*)(hsm + cl * 72 + sg * 8);
#pragma unroll
            for (int q = 0; q < 4; q++) {
                float4 v = hr[q];
                hv[q * 4 + 0] = v.x; hv[q * 4 + 1] = v.y;
                hv[q * 4 + 2] = v.z; hv[q * 4 + 3] = v.w;
            }
#pragma unroll
            for (int t = 0; t < 9; t++) {
                const float* wp = wsm + (cl * 9 + t) * 256 + ucg * 8;
                float4 wa = *(const float4*)wp;
                float4 wb = *(const float4*)(wp + 4);
                float wv[8] = {wa.x, wa.y, wa.z, wa.w, wb.x, wb.y, wb.z, wb.w};
#pragma unroll
                for (int j = 0; j < 4; j++) {
                    float h = hv[2 * j + t];
#pragma unroll
                    for (int i = 0; i < 8; i++) acc[i][j] = fmaf(wv[i], h, acc[i][j]);
                }
            }
        }
    }
    __syncthreads();
    float* psm = sbuf;
    float bi[8];
#pragma unroll
    for (int i = 0; i < 8; i++) bi[i] = bias[ucg * 8 + i];
#pragma unroll
    for (int j = 0; j < 4; j++)
#pragma unroll
        for (int i = 0; i < 8; i++)
            psm[(sg * 4 + j) * 257 + ucg * 8 + i] = acc[i][j] + bi[i];
    __syncthreads();
    int u = tid >> 5, sl = tid & 31;
    const float* pr = psm + sl * 257 + u * 32;
    float sq = 0.f;
#pragma unroll
    for (int c = 0; c < 32; c++) { float pv = pr[c]; sq += pv * pv; }
    float sc = (sq / (1.f + sq)) * rsqrtf(sq + 1e-8f);
    float* dst = g_p + (((size_t)(b * U_ + u)) * S_ + sb + sl) * C_;
#pragma unroll
    for (int c = 0; c < 32; c++) dst[c] = pr[c] * sc;
}

// ---------------- u_hat: per (u,b) block, all 9 k, bf16 out, coalesced stores -------
// 128 threads; thread handles rows s=tid and s=tid+128. W[u] (9 x 32x32) in smem.
// Output staged in smem (pad 17 for bank-free writes), then written coalesced.
__global__ void __launch_bounds__(128) k_uhat(const float* __restrict__ W) {
    __shared__ float wsm[9 * 1024];       // 36 KB
    __shared__ unsigned stage[128 * 17];  // 8.5 KB, bf16x2 staging for 128 rows
    int u = blockIdx.x, b = blockIdx.y;
    int tid = threadIdx.x;
    const float4* Wu = (const float4*)(W + (size_t)u * K_ * 1024);
    for (int i = tid; i < 9 * 256; i += 128) ((float4*)wsm)[i] = Wu[i];
    __syncthreads();

    const float4* p0 = (const float4*)(g_p + ((size_t)(b * U_ + u)) * S_ * C_ + (size_t)tid * C_);
    const float4* p1 = (const float4*)(g_p + ((size_t)(b * U_ + u)) * S_ * C_ + (size_t)(tid + 128) * C_);
    unsigned* uhb = (unsigned*)g_uh;

#pragma unroll 1
    for (int k = 0; k < K_; k++) {
        const float* wk = wsm + k * 1024;
        float a0[32], a1[32];
#pragma unroll
        for (int c = 0; c < 32; c++) { a0[c] = 0.f; a1[c] = 0.f; }
#pragma unroll 1
        for (int c4 = 0; c4 < 8; c4++) {
            float4 va = p0[c4], vb = p1[c4];
            float fa[4] = {va.x, va.y, va.z, va.w};
            float fb[4] = {vb.x, vb.y, vb.z, vb.w};
#pragma unroll
            for (int cc = 0; cc < 4; cc++) {
                float xa = fa[cc], xb = fb[cc];
                const float4* wr = (const float4*)(wk + (c4 * 4 + cc) * 32);
#pragma unroll
                for (int q = 0; q < 8; q++) {
                    float4 wv = wr[q];
                    a0[4 * q + 0] = fmaf(xa, wv.x, a0[4 * q + 0]);
                    a0[4 * q + 1] = fmaf(xa, wv.y, a0[4 * q + 1]);
                    a0[4 * q + 2] = fmaf(xa, wv.z, a0[4 * q + 2]);
                    a0[4 * q + 3] = fmaf(xa, wv.w, a0[4 * q + 3]);
                    a1[4 * q + 0] = fmaf(xb, wv.x, a1[4 * q + 0]);
                    a1[4 * q + 1] = fmaf(xb, wv.y, a1[4 * q + 1]);
                    a1[4 * q + 2] = fmaf(xb, wv.z, a1[4 * q + 2]);
                    a1[4 * q + 3] = fmaf(xb, wv.w, a1[4 * q + 3]);
                }
            }
        }
        size_t ubase = ((size_t)((b * U_ + u) * K_ + k)) * (S_ * C_ / 2); // uint offset
#pragma unroll 1
        for (int h = 0; h < 2; h++) {
            const float* ar = h ? a1 : a0;
#pragma unroll
            for (int q = 0; q < 16; q++) {
                __nv_bfloat162 hv = __floats2bfloat162_rn(ar[2 * q], ar[2 * q + 1]);
                stage[tid * 17 + q] = *(unsigned*)&hv;
            }
            __syncthreads();
            unsigned* dst = uhb + ubase + h * 2048;
            for (int i = tid; i < 2048; i += 128)
                dst[i] = stage[(i >> 4) * 17 + (i & 15)];
            __syncthreads();
        }
    }
}

// ---------------- routing iteration (u_hat in bf16) ----------------
// Logits constant over S -> per-(b,u,k) coupling scalars.
// PHASE 0: c uniform, writes logA. PHASE 1: c=softmax(logA), writes logB.
// PHASE 2: c=softmax(logB), reduces mean_s(v) -> out.
__device__ __forceinline__ void bf8_to_f(uint4 r, float* f) {
    const __nv_bfloat162* hp = (const __nv_bfloat162*)&r;
#pragma unroll
    for (int j = 0; j < 4; j++) {
        float2 t = __bfloat1622float2(hp[j]);
        f[2 * j] = t.x; f[2 * j + 1] = t.y;
    }
}

template <int PHASE>
__global__ void __launch_bounds__(256) k_route(float* __restrict__ out) {
    __shared__ float cs[8];
    __shared__ float sbuf[8448];
    int k = blockIdx.x, b = blockIdx.y, s = threadIdx.x;

    if (PHASE == 0) {
        if (s < 8) cs[s] = 1.f / 9.f;
    } else {
        const float* lin = (PHASE == 1) ? g_logA : g_logB;
        if (s < 8) {
            const float* lp = lin + (b * U_ + s) * K_;
            float lg[9], m = -1e30f;
#pragma unroll
            for (int i = 0; i < 9; i++) { lg[i] = lp[i]; m = fmaxf(m, lg[i]); }
            float sum = 0.f;
#pragma unroll
            for (int i = 0; i < 9; i++) sum += expf(lg[i] - m);
            cs[s] = expf(lg[k] - m) / sum;
        }
    }
    __syncthreads();

    const unsigned* uhb = (const unsigned*)g_uh;
    float sa[32];
#pragma unroll
    for (int c = 0; c < 32; c++) sa[c] = 0.f;
#pragma unroll 1
    for (int u = 0; u < 8; u++) {
        float cu = cs[u];
        const uint4* up = (const uint4*)(uhb +
            ((size_t)(((b * U_ + u) * K_ + k) * S_ + s)) * (C_ / 2));
#pragma unroll
        for (int q = 0; q < 4; q++) {
            float f[8];
            bf8_to_f(up[q], f);
#pragma unroll
            for (int j = 0; j < 8; j++) sa[q * 8 + j] = fmaf(cu, f[j], sa[q * 8 + j]);
        }
    }
    float sq = 0.f;
#pragma unroll
    for (int c = 0; c < 32; c++) sq += sa[c] * sa[c];
    float sc = (sq / (1.f + sq)) * rsqrtf(sq + 1e-8f);
    float v8[32];
#pragma unroll
    for (int c = 0; c < 32; c++) v8[c] = sa[c] * sc;

    if (PHASE < 2) {
#pragma unroll 1
        for (int u = 0; u < 8; u++) {
            const uint4* up = (const uint4*)(uhb +
                ((size_t)(((b * U_ + u) * K_ + k) * S_ + s)) * (C_ / 2));
            float d = 0.f;
#pragma unroll
            for (int q = 0; q < 4; q++) {
                float f[8];
                bf8_to_f(up[q], f);
#pragma unroll
                for (int j = 0; j < 8; j++) d = fmaf(f[j], v8[q * 8 + j], d);
            }
            sbuf[u * 256 + s] = d;
        }
        __syncthreads();
        int warp = s >> 5, lane = s & 31;
        float t = 0.f;
#pragma unroll
        for (int j = 0; j < 8; j++) t += sbuf[warp * 256 + lane + j * 32];
#pragma unroll
        for (int off = 16; off > 0; off >>= 1) t += __shfl_xor_sync(0xffffffffu, t, off);
        if (lane == 0) {
            int li = (b * U_ + warp) * K_ + k;
            if (PHASE == 0) g_logA[li] = t;
            else            g_logB[li] = g_logA[li] + t;
        }
    } else {
#pragma unroll
        for (int c = 0; c < 32; c++) sbuf[s * 33 + c] = v8[c];
        __syncthreads();
        int col = s & 31, seg = s >> 5;
        float t = 0.f;
#pragma unroll
        for (int r = 0; r < 32; r++) t += sbuf[(seg * 32 + r) * 33 + col];
        __syncthreads();
        sbuf[seg * 32 + col] = t;
        __syncthreads();
        if (s < 32) {
            float acc = 0.f;
#pragma unroll
            for (int g = 0; g < 8; g++) acc += sbuf[g * 32 + s];
            out[(b * K_ + k) * C_ + s] = acc * (1.f / 256.f);
        }
    }
}

// ---------------- launch ----------------
extern "C" void kernel_launch(void* const* d_in, const int* in_sizes, int n_in,
                              void* d_out, int out_size) {
    const int*   x    = (const int*)d_in[0];
    const float* mask = (const float*)d_in[1];
    const float* emb  = (const float*)d_in[2];
    const float* c1w  = (const float*)d_in[3];
    const float* c1b  = (const float*)d_in[4];
    const float* pw   = (const float*)d_in[5];
    const float* pb   = (const float*)d_in[6];
    const float* W    = (const float*)d_in[7];
    float* out = (float*)d_out;

    k_prep<<<(E_ * 9 * C_ + C_ * 9 * 256 + 255) / 256, 256>>>(c1w, pw);
    k_conv1<<<dim3(L_ / 128, B_), 128>>>(x, mask, emb, c1b);
    k_prim<<<dim3(S_ / 32, B_), 256>>>(pb);
    k_uhat<<<dim3(U_, B_), 128>>>(W);
    k_route<0><<<dim3(K_, B_), 256>>>(out);
    k_route<1><<<dim3(K_, B_), 256>>>(out);
    k_route<2><<<dim3(K_, B_), 256>>>(out);
}

// round 9
// speedup vs baseline: 1.2665x; 1.0177x over previous
#include <cuda_runtime.h>
#include <cuda_bf16.h>
#include <math.h>

#define B_ 64
#define L_ 512
#define E_ 512
#define C_ 32
#define U_ 8
#define K_ 9
#define S_ 256

// ---------------- scratch (device globals; no allocation) ----------------
__device__ float g_h[(size_t)B_ * L_ * C_];            // 4 MB   conv1 output [B,L,C]
__device__ float g_p[(size_t)B_ * U_ * S_ * C_];       // 16 MB  squashed primary caps [B,U,S,C]
__device__ __nv_bfloat16 g_uh[(size_t)B_ * U_ * K_ * S_ * C_]; // 75 MB u_hat bf16 [B,U,K,cp,S,(2)]
__device__ float g_c1wT[E_ * 9 * C_];                  // conv1 weights transposed [e][t][co]
__device__ float g_pwT[C_ * 9 * U_ * C_];              // prim weights transposed [ci][t][uc]
__device__ float g_logA[B_ * U_ * K_];                 // routing logits ping
__device__ float g_logB[B_ * U_ * K_];                 // routing logits pong

// ---------------- weight transposes ----------------
__global__ void k_prep(const float* __restrict__ c1w, const float* __restrict__ pw) {
    int i = blockIdx.x * 256 + threadIdx.x;
    if (i < E_ * 9 * C_) {
        int e = i / (9 * C_), t = (i / C_) % 9, co = i % C_;
        g_c1wT[i] = c1w[(co * E_ + e) * 9 + t];
    } else {
        int j = i - E_ * 9 * C_;
        if (j < C_ * 9 * 256) {
            int ci = j / (9 * 256), t = (j / 256) % 9, uc = j % 256;
            g_pwT[j] = pw[(uc * C_ + ci) * 9 + t];
        }
    }
}

// ---------------- conv1 (fused embedding gather): E=512 -> C=32, k=9, pad 4, ReLU ----
__global__ void __launch_bounds__(128) k_conv1(const int* __restrict__ x,
                                               const float* __restrict__ mask,
                                               const float* __restrict__ emb,
                                               const float* __restrict__ bias) {
    __shared__ float esm[16 * 136];       // [e_local][row], rows = 128 + 8
    __shared__ float wsm[16 * 9 * 32];    // [e_local][t][co]
    __shared__ int   tsm[136];
    __shared__ float msm[136];
    int b = blockIdx.y;
    int lbase = blockIdx.x * 128;
    int tid = threadIdx.x, warp = tid >> 5, lane = tid & 31;
    int l0 = lane * 4;

    for (int row = tid; row < 136; row += 128) {
        int l = lbase - 4 + row;
        if (l >= 0 && l < L_) {
            tsm[row] = x[b * L_ + l];
            msm[row] = mask[b * L_ + l];
        } else {
            tsm[row] = -1;
            msm[row] = 0.f;
        }
    }

    float acc[8][4];
#pragma unroll
    for (int i = 0; i < 8; i++)
#pragma unroll
        for (int j = 0; j < 4; j++) acc[i][j] = 0.f;

    __syncthreads();

    for (int ch = 0; ch < 32; ch++) {
        int ec = ch * 16;
        if (ch) __syncthreads();
        for (int idx = tid; idx < 136 * 4; idx += 128) {
            int row = idx >> 2, q = idx & 3;
            int tok = tsm[row];
            float4 v = make_float4(0.f, 0.f, 0.f, 0.f);
            if (tok >= 0) {
                v = *(const float4*)(emb + (size_t)tok * E_ + ec + q * 4);
                float m = msm[row];
                v.x *= m; v.y *= m; v.z *= m; v.w *= m;
            }
            esm[(q * 4 + 0) * 136 + row] = v.x;
            esm[(q * 4 + 1) * 136 + row] = v.y;
            esm[(q * 4 + 2) * 136 + row] = v.z;
            esm[(q * 4 + 3) * 136 + row] = v.w;
        }
        {
            const float4* src = (const float4*)(g_c1wT + ec * 288);
            float4* dst = (float4*)wsm;
            for (int idx = tid; idx < 1152; idx += 128) dst[idx] = src[idx];
        }
        __syncthreads();
#pragma unroll 1
        for (int el = 0; el < 16; el++) {
            float ev[12];
            const float4* er = (const float4*)(esm + el * 136 + l0);
#pragma unroll
            for (int q = 0; q < 3; q++) {
                float4 v = er[q];
                ev[q * 4 + 0] = v.x; ev[q * 4 + 1] = v.y;
                ev[q * 4 + 2] = v.z; ev[q * 4 + 3] = v.w;
            }
#pragma unroll
            for (int t = 0; t < 9; t++) {
                const float* wp = wsm + (el * 9 + t) * 32 + warp * 8;
                float4 wa = *(const float4*)wp;
                float4 wb = *(const float4*)(wp + 4);
                float wv[8] = {wa.x, wa.y, wa.z, wa.w, wb.x, wb.y, wb.z, wb.w};
#pragma unroll
                for (int j = 0; j < 4; j++) {
                    float e = ev[j + t];
#pragma unroll
                    for (int i = 0; i < 8; i++) acc[i][j] = fmaf(wv[i], e, acc[i][j]);
                }
            }
        }
    }
    float bi[8];
#pragma unroll
    for (int i = 0; i < 8; i++) bi[i] = bias[warp * 8 + i];
#pragma unroll
    for (int j = 0; j < 4; j++) {
        int l = lbase + l0 + j;
        float4 o0, o1;
        o0.x = fmaxf(acc[0][j] + bi[0], 0.f);
        o0.y = fmaxf(acc[1][j] + bi[1], 0.f);
        o0.z = fmaxf(acc[2][j] + bi[2], 0.f);
        o0.w = fmaxf(acc[3][j] + bi[3], 0.f);
        o1.x = fmaxf(acc[4][j] + bi[4], 0.f);
        o1.y = fmaxf(acc[5][j] + bi[5], 0.f);
        o1.z = fmaxf(acc[6][j] + bi[6], 0.f);
        o1.w = fmaxf(acc[7][j] + bi[7], 0.f);
        float* dst = g_h + ((size_t)(b * L_ + l)) * C_ + warp * 8;
        *(float4*)dst = o0;
        *(float4*)(dst + 4) = o1;
    }
}

// ---------------- primary caps conv: 32 -> 256, k=9, pad 4, stride 2, + squash ----------------
__global__ void __launch_bounds__(256) k_prim(const float* __restrict__ bias) {
    __shared__ float sbuf[9504];
    int b = blockIdx.y;
    int sb = blockIdx.x * 32;
    int tid = threadIdx.x;
    int ucg = tid >> 3, sg = tid & 7;
    float acc[8][4];
#pragma unroll
    for (int i = 0; i < 8; i++)
#pragma unroll
        for (int j = 0; j < 4; j++) acc[i][j] = 0.f;

    float* hsm = sbuf;
    float* wsm = sbuf + 288;
    int lorg = 2 * sb - 4;

    for (int ch = 0; ch < 8; ch++) {
        int ci0 = ch * 4;
        __syncthreads();
        for (int row = tid; row < 72; row += 256) {
            int l = lorg + row;
            float4 v = make_float4(0.f, 0.f, 0.f, 0.f);
            if (l >= 0 && l < L_)
                v = *(const float4*)(g_h + ((size_t)(b * L_ + l)) * C_ + ci0);
            hsm[row] = v.x;
            hsm[72 + row] = v.y;
            hsm[144 + row] = v.z;
            hsm[216 + row] = v.w;
        }
        {
            const float4* src = (const float4*)(g_pwT + ci0 * 2304);
            float4* dst = (float4*)wsm;
            for (int idx = tid; idx < 2304; idx += 256) dst[idx] = src[idx];
        }
        __syncthreads();
#pragma unroll
        for (int cl = 0; cl < 4; cl++) {
            float hv[16];
            const float4* hr = (const float4*)(hsm + cl * 72 + sg * 8);
#pragma unroll
            for (int q = 0; q < 4; q++) {
                float4 v = hr[q];
                hv[q * 4 + 0] = v.x; hv[q * 4 + 1] = v.y;
                hv[q * 4 + 2] = v.z; hv[q * 4 + 3] = v.w;
            }
#pragma unroll
            for (int t = 0; t < 9; t++) {
                const float* wp = wsm + (cl * 9 + t) * 256 + ucg * 8;
                float4 wa = *(const float4*)wp;
                float4 wb = *(const float4*)(wp + 4);
                float wv[8] = {wa.x, wa.y, wa.z, wa.w, wb.x, wb.y, wb.z, wb.w};
#pragma unroll
                for (int j = 0; j < 4; j++) {
                    float h = hv[2 * j + t];
#pragma unroll
                    for (int i = 0; i < 8; i++) acc[i][j] = fmaf(wv[i], h, acc[i][j]);
                }
            }
        }
    }
    __syncthreads();
    float* psm = sbuf;
    float bi[8];
#pragma unroll
    for (int i = 0; i < 8; i++) bi[i] = bias[ucg * 8 + i];
#pragma unroll
    for (int j = 0; j < 4; j++)
#pragma unroll
        for (int i = 0; i < 8; i++)
            psm[(sg * 4 + j) * 257 + ucg * 8 + i] = acc[i][j] + bi[i];
    __syncthreads();
    int u = tid >> 5, sl = tid & 31;
    const float* pr = psm + sl * 257 + u * 32;
    float sq = 0.f;
#pragma unroll
    for (int c = 0; c < 32; c++) { float pv = pr[c]; sq += pv * pv; }
    float sc = (sq / (1.f + sq)) * rsqrtf(sq + 1e-8f);
    float* dst = g_p + (((size_t)(b * U_ + u)) * S_ + sb + sl) * C_;
#pragma unroll
    for (int c = 0; c < 32; c++) dst[c] = pr[c] * sc;
}

// ---------------- u_hat: per (u,b) block, 256 threads (one s-row each) -------------
// p tile staged coalesced into smem once; p row held in registers across all 9 k.
// u_hat layout [b,u,k][cp][s] as bf16x2 -> stores AND routing loads fully coalesced.
__global__ void __launch_bounds__(256) k_uhat(const float* __restrict__ W) {
    __shared__ float wsm[1024];           // W[u,k] 32x32, reloaded per k
    __shared__ float psm[256 * 33];       // p tile, stride-33 pad (conflict-free rows)
    int u = blockIdx.x, b = blockIdx.y;
    int tid = threadIdx.x;

    // cooperative coalesced load of p tile (256 rows x 32 floats = 2048 float4)
    const float4* src = (const float4*)(g_p + ((size_t)(b * U_ + u)) * S_ * C_);
    for (int i = tid; i < 2048; i += 256) {
        float4 v = src[i];
        float* d = psm + (i >> 3) * 33 + (i & 7) * 4;
        d[0] = v.x; d[1] = v.y; d[2] = v.z; d[3] = v.w;
    }
    __syncthreads();
    float p[32];
#pragma unroll
    for (int c = 0; c < 32; c++) p[c] = psm[tid * 33 + c];

    unsigned* uhb = (unsigned*)g_uh;
    const float4* Wg = (const float4*)(W + (size_t)u * K_ * 1024);

#pragma unroll 1
    for (int k = 0; k < K_; k++) {
        __syncthreads();                      // all reads of previous wsm done
        ((float4*)wsm)[tid & 255] = Wg[k * 256 + (tid & 255)];
        __syncthreads();
        float acc[32];
#pragma unroll
        for (int d = 0; d < 32; d++) acc[d] = 0.f;
#pragma unroll 4
        for (int c = 0; c < 32; c++) {
            float x = p[c];
            const float4* wr = (const float4*)(wsm + c * 32);
#pragma unroll
            for (int q = 0; q < 8; q++) {
                float4 wv = wr[q];
                acc[4 * q + 0] = fmaf(x, wv.x, acc[4 * q + 0]);
                acc[4 * q + 1] = fmaf(x, wv.y, acc[4 * q + 1]);
                acc[4 * q + 2] = fmaf(x, wv.z, acc[4 * q + 2]);
                acc[4 * q + 3] = fmaf(x, wv.w, acc[4 * q + 3]);
            }
        }
        unsigned* dst = uhb + ((size_t)((b * U_ + u) * K_ + k)) * 4096 + tid;
#pragma unroll
        for (int cp = 0; cp < 16; cp++) {
            __nv_bfloat162 hv = __floats2bfloat162_rn(acc[2 * cp], acc[2 * cp + 1]);
            dst[cp * 256] = *(unsigned*)&hv;
        }
    }
}

// ---------------- routing iteration (u_hat bf16, [b,u,k][cp][s] layout) ------------
// Logits constant over S -> per-(b,u,k) coupling scalars.
// PHASE 0: c uniform, writes logA. PHASE 1: c=softmax(logA), writes logB.
// PHASE 2: c=softmax(logB), reduces mean_s(v) -> out.
template <int PHASE>
__global__ void __launch_bounds__(256) k_route(float* __restrict__ out) {
    __shared__ float cs[8];
    __shared__ float sbuf[8448];
    int k = blockIdx.x, b = blockIdx.y, s = threadIdx.x;

    if (PHASE == 0) {
        if (s < 8) cs[s] = 1.f / 9.f;
    } else {
        const float* lin = (PHASE == 1) ? g_logA : g_logB;
        if (s < 8) {
            const float* lp = lin + (b * U_ + s) * K_;
            float lg[9], m = -1e30f;
#pragma unroll
            for (int i = 0; i < 9; i++) { lg[i] = lp[i]; m = fmaxf(m, lg[i]); }
            float sum = 0.f;
#pragma unroll
            for (int i = 0; i < 9; i++) sum += expf(lg[i] - m);
            cs[s] = expf(lg[k] - m) / sum;
        }
    }
    __syncthreads();

    const unsigned* uhb = (const unsigned*)g_uh;
    float sa[32];
#pragma unroll
    for (int c = 0; c < 32; c++) sa[c] = 0.f;
#pragma unroll 1
    for (int u = 0; u < 8; u++) {
        float cu = cs[u];
        const unsigned* base = uhb + ((size_t)((b * U_ + u) * K_ + k)) * 4096 + s;
#pragma unroll
        for (int cp = 0; cp < 16; cp++) {
            unsigned r = base[cp * 256];
            float2 t = __bfloat1622float2(*(__nv_bfloat162*)&r);
            sa[2 * cp]     = fmaf(cu, t.x, sa[2 * cp]);
            sa[2 * cp + 1] = fmaf(cu, t.y, sa[2 * cp + 1]);
        }
    }
    float sq = 0.f;
#pragma unroll
    for (int c = 0; c < 32; c++) sq += sa[c] * sa[c];
    float sc = (sq / (1.f + sq)) * rsqrtf(sq + 1e-8f);
    float v8[32];
#pragma unroll
    for (int c = 0; c < 32; c++) v8[c] = sa[c] * sc;

    if (PHASE < 2) {
#pragma unroll 1
        for (int u = 0; u < 8; u++) {
            const unsigned* base = uhb + ((size_t)((b * U_ + u) * K_ + k)) * 4096 + s;
            float d = 0.f;
#pragma unroll
            for (int cp = 0; cp < 16; cp++) {
                unsigned r = base[cp * 256];
                float2 t = __bfloat1622float2(*(__nv_bfloat162*)&r);
                d = fmaf(t.x, v8[2 * cp], d);
                d = fmaf(t.y, v8[2 * cp + 1], d);
            }
            sbuf[u * 256 + s] = d;
        }
        __syncthreads();
        int warp = s >> 5, lane = s & 31;
        float t = 0.f;
#pragma unroll
        for (int j = 0; j < 8; j++) t += sbuf[warp * 256 + lane + j * 32];
#pragma unroll
        for (int off = 16; off > 0; off >>= 1) t += __shfl_xor_sync(0xffffffffu, t, off);
        if (lane == 0) {
            int li = (b * U_ + warp) * K_ + k;
            if (PHASE == 0) g_logA[li] = t;
            else            g_logB[li] = g_logA[li] + t;
        }
    } else {
#pragma unroll
        for (int c = 0; c < 32; c++) sbuf[s * 33 + c] = v8[c];
        __syncthreads();
        int col = s & 31, seg = s >> 5;
        float t = 0.f;
#pragma unroll
        for (int r = 0; r < 32; r++) t += sbuf[(seg * 32 + r) * 33 + col];
        __syncthreads();
        sbuf[seg * 32 + col] = t;
        __syncthreads();
        if (s < 32) {
            float acc = 0.f;
#pragma unroll
            for (int g = 0; g < 8; g++) acc += sbuf[g * 32 + s];
            out[(b * K_ + k) * C_ + s] = acc * (1.f / 256.f);
        }
    }
}

// ---------------- launch ----------------
extern "C" void kernel_launch(void* const* d_in, const int* in_sizes, int n_in,
                              void* d_out, int out_size) {
    const int*   x    = (const int*)d_in[0];
    const float* mask = (const float*)d_in[1];
    const float* emb  = (const float*)d_in[2];
    const float* c1w  = (const float*)d_in[3];
    const float* c1b  = (const float*)d_in[4];
    const float* pw   = (const float*)d_in[5];
    const float* pb   = (const float*)d_in[6];
    const float* W    = (const float*)d_in[7];
    float* out = (float*)d_out;

    k_prep<<<(E_ * 9 * C_ + C_ * 9 * 256 + 255) / 256, 256>>>(c1w, pw);
    k_conv1<<<dim3(L_ / 128, B_), 128>>>(x, mask, emb, c1b);
    k_prim<<<dim3(S_ / 32, B_), 256>>>(pb);
    k_uhat<<<dim3(U_, B_), 256>>>(W);
    k_route<0><<<dim3(K_, B_), 256>>>(out);
    k_route<1><<<dim3(K_, B_), 256>>>(out);
    k_route<2><<<dim3(K_, B_), 256>>>(out);
}

// round 11
// speedup vs baseline: 1.7383x; 1.3726x over previous
#include <cuda_runtime.h>
#include <cuda_bf16.h>
#include <math.h>
#include <stdint.h>

#define B_ 64
#define L_ 512
#define E_ 512
#define C_ 32
#define U_ 8
#define K_ 9
#define S_ 256

// ---------------- scratch (device globals; no allocation) ----------------
__device__ float g_h[(size_t)B_ * L_ * C_];            // 4 MB   conv1 output [B,L,C]
__device__ float g_p[(size_t)B_ * U_ * S_ * C_];       // 16 MB  squashed primary caps
__device__ __nv_bfloat16 g_uh[(size_t)B_ * U_ * K_ * S_ * C_]; // 75 MB u_hat bf16
__device__ __nv_bfloat16 g_w2[8 * 288 * 64];           // conv1 W2 bf16, [chunk][n=t*32+co][k]
__device__ float g_pwT[C_ * 9 * U_ * C_];              // prim weights transposed [ci][t][uc]
__device__ float g_logA[B_ * U_ * K_];
__device__ float g_logB[B_ * U_ * K_];

__device__ __forceinline__ uint32_t smem_u32(const void* p) {
    uint32_t a;
    asm("{ .reg .u64 t; cvta.to.shared.u64 t, %1; cvt.u32.u64 %0, t; }" : "=r"(a) : "l"(p));
    return a;
}

// ---------------- weight prep: W2 bf16 [chunk][288][64] + prim transpose ----------------
__global__ void k_prep(const float* __restrict__ c1w, const float* __restrict__ pw) {
    int i = blockIdx.x * 256 + threadIdx.x;
    if (i < 288 * 512) {
        int n = i >> 9, e = i & 511;
        int t = n >> 5, co = n & 31;
        float val = c1w[(co * 512 + e) * 9 + t];
        g_w2[(size_t)(e >> 6) * 288 * 64 + n * 64 + (e & 63)] = __float2bfloat16(val);
    } else {
        int j = i - 288 * 512;
        if (j < C_ * 9 * 256) {
            int ci = j / (9 * 256), t = (j / 256) % 9, uc = j % 256;
            g_pwT[j] = pw[(uc * C_ + ci) * 9 + t];
        }
    }
}

// ---------------- conv1 via mma.sync (bf16 HMMA): Y = X @ W2^T, 9-tap epilogue -------
// Grid (5, B), 256 threads (8 warps: 2M x 4N), ~211 KB dynamic smem.
// Block cx covers h rows [120cx, 120cx+120); X rows lorg..lorg+127, lorg = 120cx-4.
__global__ void __launch_bounds__(256) k_conv1_mma(const int* __restrict__ x,
                                                   const float* __restrict__ mask,
                                                   const float* __restrict__ emb,
                                                   const float* __restrict__ bias) {
    extern __shared__ char cvsm[];
    __nv_bfloat16* As = (__nv_bfloat16*)cvsm;             // [128][72]
    __nv_bfloat16* Bs = (__nv_bfloat16*)(cvsm + 18432);   // [288][72]
    float* Ysm = (float*)(cvsm + 59904);                  // [128][292]
    int*   tsm = (int*)(cvsm + 209408);                   // [128]
    float* msm = (float*)(cvsm + 209920);                 // [128]
    float* bsm = (float*)(cvsm + 210432);                 // [32]

    int tid = threadIdx.x, lane = tid & 31, w = tid >> 5;
    int wm = w >> 2, wn = w & 3;
    int cx = blockIdx.x, b = blockIdx.y;
    int lorg = cx * 120 - 4;

    if (tid < 128) {
        int l = lorg + tid;
        if (l >= 0 && l < L_) { tsm[tid] = x[b * L_ + l]; msm[tid] = mask[b * L_ + l]; }
        else                  { tsm[tid] = -1;            msm[tid] = 0.f; }
    }
    if (tid < 32) bsm[tid] = bias[tid];

    float acc[4][9][4];
#pragma unroll
    for (int mt = 0; mt < 4; mt++)
#pragma unroll
        for (int nt = 0; nt < 9; nt++)
#pragma unroll
            for (int j = 0; j < 4; j++) acc[mt][nt][j] = 0.f;

    // ldmatrix per-lane base addresses
    uint32_t As32 = smem_u32(As), Bs32 = smem_u32(Bs);
    int rowA = wm * 64 + (((lane >> 3) & 1) << 3) + (lane & 7);
    int colA = ((lane >> 4) & 1) << 3;
    uint32_t aBase = As32 + (uint32_t)(rowA * 72 + colA) * 2;
    int rowB = wn * 72 + (lane & 7);
    int colB = ((lane >> 3) & 1) << 3;
    uint32_t bBase = Bs32 + (uint32_t)(rowB * 72 + colB) * 2;

    const float4* emb4 = (const float4*)emb;
    const uint4* w2g = (const uint4*)g_w2;

#pragma unroll 1
    for (int kc = 0; kc < 8; kc++) {
        __syncthreads();
        // stage A: gather 128 rows x 64 e (bf16)
        for (int i = tid; i < 2048; i += 256) {
            int r = i >> 4, q = i & 15;
            int tok = tsm[r];
            float4 v = make_float4(0.f, 0.f, 0.f, 0.f);
            if (tok >= 0) {
                v = emb4[(size_t)tok * 128 + kc * 16 + q];
                float m = msm[r];
                v.x *= m; v.y *= m; v.z *= m; v.w *= m;
            }
            __nv_bfloat162 h0 = __floats2bfloat162_rn(v.x, v.y);
            __nv_bfloat162 h1 = __floats2bfloat162_rn(v.z, v.w);
            uint2 pk = make_uint2(*(unsigned*)&h0, *(unsigned*)&h1);
            *(uint2*)((char*)As + r * 144 + q * 8) = pk;
        }
        // stage B: 288 rows x 64 k (bf16) from prepped global
        for (int i = tid; i < 2304; i += 256) {
            uint4 v = w2g[kc * 2304 + i];
            int n = i >> 3, seg = i & 7;
            *(uint4*)((char*)Bs + n * 144 + seg * 16) = v;
        }
        __syncthreads();
#pragma unroll
        for (int ks = 0; ks < 4; ks++) {
            uint32_t bf[9][2];
#pragma unroll
            for (int nt = 0; nt < 9; nt++) {
                uint32_t addr = bBase + (uint32_t)(nt * 576 + ks * 16) * 2;
                asm volatile("ldmatrix.sync.aligned.m8n8.x2.shared.b16 {%0,%1}, [%2];"
                             : "=r"(bf[nt][0]), "=r"(bf[nt][1]) : "r"(addr));
            }
#pragma unroll
            for (int mt = 0; mt < 4; mt++) {
                uint32_t af[4];
                uint32_t addr = aBase + (uint32_t)(mt * 1152 + ks * 16) * 2;
                asm volatile("ldmatrix.sync.aligned.m8n8.x4.shared.b16 {%0,%1,%2,%3}, [%4];"
                             : "=r"(af[0]), "=r"(af[1]), "=r"(af[2]), "=r"(af[3]) : "r"(addr));
#pragma unroll
                for (int nt = 0; nt < 9; nt++) {
                    asm volatile(
                        "mma.sync.aligned.m16n8k16.row.col.f32.bf16.bf16.f32 "
                        "{%0,%1,%2,%3}, {%4,%5,%6,%7}, {%8,%9}, {%0,%1,%2,%3};"
                        : "+f"(acc[mt][nt][0]), "+f"(acc[mt][nt][1]),
                          "+f"(acc[mt][nt][2]), "+f"(acc[mt][nt][3])
                        : "r"(af[0]), "r"(af[1]), "r"(af[2]), "r"(af[3]),
                          "r"(bf[nt][0]), "r"(bf[nt][1]));
                }
            }
        }
    }
    __syncthreads();

    // write Y fragments to smem
    int r0 = wm * 64 + (lane >> 2);
    int c0 = wn * 72 + ((lane & 3) << 1);
#pragma unroll
    for (int mt = 0; mt < 4; mt++) {
#pragma unroll
        for (int nt = 0; nt < 9; nt++) {
            int r = r0 + mt * 16, c = c0 + nt * 8;
            *(float2*)(Ysm + r * 292 + c)       = make_float2(acc[mt][nt][0], acc[mt][nt][1]);
            *(float2*)(Ysm + (r + 8) * 292 + c) = make_float2(acc[mt][nt][2], acc[mt][nt][3]);
        }
    }
    __syncthreads();

    // h[j][co] = bias + sum_t Y[j+t][t*32+co]; ReLU; store
    for (int i = tid; i < 120 * 32; i += 256) {
        int j = i >> 5, co = i & 31;
        float v = bsm[co];
#pragma unroll
        for (int t = 0; t < 9; t++) v += Ysm[(j + t) * 292 + t * 32 + co];
        int l = cx * 120 + j;
        if (l < L_) g_h[((size_t)(b * L_ + l)) * C_ + co] = fmaxf(v, 0.f);
    }
}

// ---------------- primary caps conv: 32 -> 256, k=9, pad 4, stride 2, + squash -------
__global__ void __launch_bounds__(256) k_prim(const float* __restrict__ bias) {
    __shared__ float sbuf[9504];
    int b = blockIdx.y;
    int sb = blockIdx.x * 32;
    int tid = threadIdx.x;
    int ucg = tid >> 3, sg = tid & 7;
    float acc[8][4];
#pragma unroll
    for (int i = 0; i < 8; i++)
#pragma unroll
        for (int j = 0; j < 4; j++) acc[i][j] = 0.f;

    float* hsm = sbuf;
    float* wsm = sbuf + 288;
    int lorg = 2 * sb - 4;

    for (int ch = 0; ch < 8; ch++) {
        int ci0 = ch * 4;
        __syncthreads();
        for (int row = tid; row < 72; row += 256) {
            int l = lorg + row;
            float4 v = make_float4(0.f, 0.f, 0.f, 0.f);
            if (l >= 0 && l < L_)
                v = *(const float4*)(g_h + ((size_t)(b * L_ + l)) * C_ + ci0);
            hsm[row] = v.x;
            hsm[72 + row] = v.y;
            hsm[144 + row] = v.z;
            hsm[216 + row] = v.w;
        }
        {
            const float4* src = (const float4*)(g_pwT + ci0 * 2304);
            float4* dst = (float4*)wsm;
            for (int idx = tid; idx < 2304; idx += 256) dst[idx] = src[idx];
        }
        __syncthreads();
#pragma unroll
        for (int cl = 0; cl < 4; cl++) {
            float hv[16];
            const float4* hr = (const float4*)(hsm + cl * 72 + sg * 8);
#pragma unroll
            for (int q = 0; q < 4; q++) {
                float4 v = hr[q];
                hv[q * 4 + 0] = v.x; hv[q * 4 + 1] = v.y;
                hv[q * 4 + 2] = v.z; hv[q * 4 + 3] = v.w;
            }
#pragma unroll
            for (int t = 0; t < 9; t++) {
                const float* wp = wsm + (cl * 9 + t) * 256 + ucg * 8;
                float4 wa = *(const float4*)wp;
                float4 wb = *(const float4*)(wp + 4);
                float wv[8] = {wa.x, wa.y, wa.z, wa.w, wb.x, wb.y, wb.z, wb.w};
#pragma unroll
                for (int j = 0; j < 4; j++) {
                    float h = hv[2 * j + t];
#pragma unroll
                    for (int i = 0; i < 8; i++) acc[i][j] = fmaf(wv[i], h, acc[i][j]);
                }
            }
        }
    }
    __syncthreads();
    float* psm = sbuf;
    float bi[8];
#pragma unroll
    for (int i = 0; i < 8; i++) bi[i] = bias[ucg * 8 + i];
#pragma unroll
    for (int j = 0; j < 4; j++)
#pragma unroll
        for (int i = 0; i < 8; i++)
            psm[(sg * 4 + j) * 257 + ucg * 8 + i] = acc[i][j] + bi[i];
    __syncthreads();
    int u = tid >> 5, sl = tid & 31;
    const float* pr = psm + sl * 257 + u * 32;
    float sq = 0.f;
#pragma unroll
    for (int c = 0; c < 32; c++) { float pv = pr[c]; sq += pv * pv; }
    float sc = (sq / (1.f + sq)) * rsqrtf(sq + 1e-8f);
    float* dst = g_p + (((size_t)(b * U_ + u)) * S_ + sb + sl) * C_;
#pragma unroll
    for (int c = 0; c < 32; c++) dst[c] = pr[c] * sc;
}

// ---------------- u_hat: per (u,b) block, 256 threads (one s-row each) -------------
__global__ void __launch_bounds__(256) k_uhat(const float* __restrict__ W) {
    __shared__ float wsm[1024];
    __shared__ float psm[256 * 33];
    int u = blockIdx.x, b = blockIdx.y;
    int tid = threadIdx.x;

    const float4* src = (const float4*)(g_p + ((size_t)(b * U_ + u)) * S_ * C_);
    for (int i = tid; i < 2048; i += 256) {
        float4 v = src[i];
        float* d = psm + (i >> 3) * 33 + (i & 7) * 4;
        d[0] = v.x; d[1] = v.y; d[2] = v.z; d[3] = v.w;
    }
    __syncthreads();
    float p[32];
#pragma unroll
    for (int c = 0; c < 32; c++) p[c] = psm[tid * 33 + c];

    unsigned* uhb = (unsigned*)g_uh;
    const float4* Wg = (const float4*)(W + (size_t)u * K_ * 1024);

#pragma unroll 1
    for (int k = 0; k < K_; k++) {
        __syncthreads();
        ((float4*)wsm)[tid & 255] = Wg[k * 256 + (tid & 255)];
        __syncthreads();
        float acc[32];
#pragma unroll
        for (int d = 0; d < 32; d++) acc[d] = 0.f;
#pragma unroll 4
        for (int c = 0; c < 32; c++) {
            float xv = p[c];
            const float4* wr = (const float4*)(wsm + c * 32);
#pragma unroll
            for (int q = 0; q < 8; q++) {
                float4 wv = wr[q];
                acc[4 * q + 0] = fmaf(xv, wv.x, acc[4 * q + 0]);
                acc[4 * q + 1] = fmaf(xv, wv.y, acc[4 * q + 1]);
                acc[4 * q + 2] = fmaf(xv, wv.z, acc[4 * q + 2]);
                acc[4 * q + 3] = fmaf(xv, wv.w, acc[4 * q + 3]);
            }
        }
        unsigned* dst = uhb + ((size_t)((b * U_ + u) * K_ + k)) * 4096 + tid;
#pragma unroll
        for (int cp = 0; cp < 16; cp++) {
            __nv_bfloat162 hv = __floats2bfloat162_rn(acc[2 * cp], acc[2 * cp + 1]);
            dst[cp * 256] = *(unsigned*)&hv;
        }
    }
}

// ---------------- routing iteration (u_hat bf16, [b,u,k][cp][s] layout) ------------
template <int PHASE>
__global__ void __launch_bounds__(256) k_route(float* __restrict__ out) {
    __shared__ float cs[8];
    __shared__ float sbuf[8448];
    int k = blockIdx.x, b = blockIdx.y, s = threadIdx.x;

    if (PHASE == 0) {
        if (s < 8) cs[s] = 1.f / 9.f;
    } else {
        const float* lin = (PHASE == 1) ? g_logA : g_logB;
        if (s < 8) {
            const float* lp = lin + (b * U_ + s) * K_;
            float lg[9], m = -1e30f;
#pragma unroll
            for (int i = 0; i < 9; i++) { lg[i] = lp[i]; m = fmaxf(m, lg[i]); }
            float sum = 0.f;
#pragma unroll
            for (int i = 0; i < 9; i++) sum += expf(lg[i] - m);
            cs[s] = expf(lg[k] - m) / sum;
        }
    }
    __syncthreads();

    const unsigned* uhb = (const unsigned*)g_uh;
    float sa[32];
#pragma unroll
    for (int c = 0; c < 32; c++) sa[c] = 0.f;
#pragma unroll 1
    for (int u = 0; u < 8; u++) {
        float cu = cs[u];
        const unsigned* base = uhb + ((size_t)((b * U_ + u) * K_ + k)) * 4096 + s;
#pragma unroll
        for (int cp = 0; cp < 16; cp++) {
            unsigned r = base[cp * 256];
            float2 t = __bfloat1622float2(*(__nv_bfloat162*)&r);
            sa[2 * cp]     = fmaf(cu, t.x, sa[2 * cp]);
            sa[2 * cp + 1] = fmaf(cu, t.y, sa[2 * cp + 1]);
        }
    }
    float sq = 0.f;
#pragma unroll
    for (int c = 0; c < 32; c++) sq += sa[c] * sa[c];
    float sc = (sq / (1.f + sq)) * rsqrtf(sq + 1e-8f);
    float v8[32];
#pragma unroll
    for (int c = 0; c < 32; c++) v8[c] = sa[c] * sc;

    if (PHASE < 2) {
#pragma unroll 1
        for (int u = 0; u < 8; u++) {
            const unsigned* base = uhb + ((size_t)((b * U_ + u) * K_ + k)) * 4096 + s;
            float d = 0.f;
#pragma unroll
            for (int cp = 0; cp < 16; cp++) {
                unsigned r = base[cp * 256];
                float2 t = __bfloat1622float2(*(__nv_bfloat162*)&r);
                d = fmaf(t.x, v8[2 * cp], d);
                d = fmaf(t.y, v8[2 * cp + 1], d);
            }
            sbuf[u * 256 + s] = d;
        }
        __syncthreads();
        int warp = s >> 5, lane = s & 31;
        float t = 0.f;
#pragma unroll
        for (int j = 0; j < 8; j++) t += sbuf[warp * 256 + lane + j * 32];
#pragma unroll
        for (int off = 16; off > 0; off >>= 1) t += __shfl_xor_sync(0xffffffffu, t, off);
        if (lane == 0) {
            int li = (b * U_ + warp) * K_ + k;
            if (PHASE == 0) g_logA[li] = t;
            else            g_logB[li] = g_logA[li] + t;
        }
    } else {
#pragma unroll
        for (int c = 0; c < 32; c++) sbuf[s * 33 + c] = v8[c];
        __syncthreads();
        int col = s & 31, seg = s >> 5;
        float t = 0.f;
#pragma unroll
        for (int r = 0; r < 32; r++) t += sbuf[(seg * 32 + r) * 33 + col];
        __syncthreads();
        sbuf[seg * 32 + col] = t;
        __syncthreads();
        if (s < 32) {
            float acc = 0.f;
#pragma unroll
            for (int g = 0; g < 8; g++) acc += sbuf[g * 32 + s];
            out[(b * K_ + k) * C_ + s] = acc * (1.f / 256.f);
        }
    }
}

// ---------------- launch ----------------
extern "C" void kernel_launch(void* const* d_in, const int* in_sizes, int n_in,
                              void* d_out, int out_size) {
    const int*   x    = (const int*)d_in[0];
    const float* mask = (const float*)d_in[1];
    const float* emb  = (const float*)d_in[2];
    const float* c1w  = (const float*)d_in[3];
    const float* c1b  = (const float*)d_in[4];
    const float* pw   = (const float*)d_in[5];
    const float* pb   = (const float*)d_in[6];
    const float* W    = (const float*)d_in[7];
    float* out = (float*)d_out;

    const int CONV_SMEM = 210560;
    static int attr_set = 0;
    if (!attr_set) {
        cudaFuncSetAttribute(k_conv1_mma, cudaFuncAttributeMaxDynamicSharedMemorySize, CONV_SMEM);
        attr_set = 1;
    }

    k_prep<<<(288 * 512 + C_ * 9 * 256 + 255) / 256, 256>>>(c1w, pw);
    k_conv1_mma<<<dim3(5, B_), 256, CONV_SMEM>>>(x, mask, emb, c1b);
    k_prim<<<dim3(S_ / 32, B_), 256>>>(pb);
    k_uhat<<<dim3(U_, B_), 256>>>(W);
    k_route<0><<<dim3(K_, B_), 256>>>(out);
    k_route<1><<<dim3(K_, B_), 256>>>(out);
    k_route<2><<<dim3(K_, B_), 256>>>(out);
}

// round 13
// speedup vs baseline: 2.0622x; 1.1864x over previous
#include <cuda_runtime.h>
#include <cuda_bf16.h>
#include <math.h>
#include <stdint.h>

#define B_ 64
#define L_ 512
#define E_ 512
#define C_ 32
#define U_ 8
#define K_ 9
#define S_ 256

// ---------------- scratch (device globals; no allocation) ----------------
__device__ float g_h[(size_t)B_ * L_ * C_];            // 4 MB   conv1 output [B,L,C]
__device__ float g_p[(size_t)B_ * U_ * S_ * C_];       // 16 MB  squashed primary caps
__device__ __nv_bfloat16 g_uh[(size_t)B_ * U_ * K_ * S_ * C_]; // 75 MB u_hat bf16 [b,u,k][cp][s]
__device__ __nv_bfloat16 g_w2[8 * 288 * 64];           // conv1 W2 bf16, [chunk][n=t*32+co][k]
__device__ float g_wp[U_ * 288 * 32];                  // uhat Wpack fp32, [u][n=kk*32+d][c]
__device__ float g_pwT[C_ * 9 * U_ * C_];              // prim weights transposed [ci][t][uc]
__device__ float g_logA[B_ * U_ * K_];
__device__ float g_logB[B_ * U_ * K_];

__device__ __forceinline__ uint32_t smem_u32(const void* p) {
    uint32_t a;
    asm("{ .reg .u64 t; cvta.to.shared.u64 t, %1; cvt.u32.u64 %0, t; }" : "=r"(a) : "l"(p));
    return a;
}
__device__ __forceinline__ uint32_t f2tf32(float f) {
    uint32_t r;
    asm("cvt.rna.tf32.f32 %0, %1;" : "=r"(r) : "f"(f));
    return r;
}

// ---------------- weight prep: conv W2 (bf16), uhat Wpack (fp32), prim transpose ------
__global__ void k_prep(const float* __restrict__ c1w, const float* __restrict__ pw,
                       const float* __restrict__ W) {
    int i = blockIdx.x * 256 + threadIdx.x;
    if (i < 288 * 512) {
        int n = i >> 9, e = i & 511;
        int t = n >> 5, co = n & 31;
        float val = c1w[(co * 512 + e) * 9 + t];
        g_w2[(size_t)(e >> 6) * 288 * 64 + n * 64 + (e & 63)] = __float2bfloat16(val);
        return;
    }
    int j = i - 288 * 512;
    if (j < C_ * 9 * 256) {
        int ci = j / (9 * 256), t = (j / 256) % 9, uc = j % 256;
        g_pwT[j] = pw[(uc * C_ + ci) * 9 + t];
        return;
    }
    int m = j - C_ * 9 * 256;
    if (m < U_ * 288 * 32) {
        int u = m / 9216, rem = m % 9216;
        int n = rem >> 5, c = rem & 31;
        int kk = n >> 5, d = n & 31;
        g_wp[(size_t)(u * 288 + n) * 32 + c] = W[(size_t)(((u * 9 + kk) * 32 + c)) * 32 + d];
    }
}

// ---------------- conv1 via mma.sync (bf16 HMMA): Y = X @ W2^T, 9-tap epilogue -------
__global__ void __launch_bounds__(256) k_conv1_mma(const int* __restrict__ x,
                                                   const float* __restrict__ mask,
                                                   const float* __restrict__ emb,
                                                   const float* __restrict__ bias) {
    extern __shared__ char cvsm[];
    __nv_bfloat16* As = (__nv_bfloat16*)cvsm;             // [128][72]
    __nv_bfloat16* Bs = (__nv_bfloat16*)(cvsm + 18432);   // [288][72]
    float* Ysm = (float*)(cvsm + 59904);                  // [128][292]
    int*   tsm = (int*)(cvsm + 209408);
    float* msm = (float*)(cvsm + 209920);
    float* bsm = (float*)(cvsm + 210432);

    int tid = threadIdx.x, lane = tid & 31, w = tid >> 5;
    int wm = w >> 2, wn = w & 3;
    int cx = blockIdx.x, b = blockIdx.y;
    int lorg = cx * 120 - 4;

    if (tid < 128) {
        int l = lorg + tid;
        if (l >= 0 && l < L_) { tsm[tid] = x[b * L_ + l]; msm[tid] = mask[b * L_ + l]; }
        else                  { tsm[tid] = -1;            msm[tid] = 0.f; }
    }
    if (tid < 32) bsm[tid] = bias[tid];

    float acc[4][9][4];
#pragma unroll
    for (int mt = 0; mt < 4; mt++)
#pragma unroll
        for (int nt = 0; nt < 9; nt++)
#pragma unroll
            for (int j = 0; j < 4; j++) acc[mt][nt][j] = 0.f;

    uint32_t As32 = smem_u32(As), Bs32 = smem_u32(Bs);
    int rowA = wm * 64 + (((lane >> 3) & 1) << 3) + (lane & 7);
    int colA = ((lane >> 4) & 1) << 3;
    uint32_t aBase = As32 + (uint32_t)(rowA * 72 + colA) * 2;
    int rowB = wn * 72 + (lane & 7);
    int colB = ((lane >> 3) & 1) << 3;
    uint32_t bBase = Bs32 + (uint32_t)(rowB * 72 + colB) * 2;

    const float4* emb4 = (const float4*)emb;
    const uint4* w2g = (const uint4*)g_w2;

#pragma unroll 1
    for (int kc = 0; kc < 8; kc++) {
        __syncthreads();
        for (int i = tid; i < 2048; i += 256) {
            int r = i >> 4, q = i & 15;
            int tok = tsm[r];
            float4 v = make_float4(0.f, 0.f, 0.f, 0.f);
            if (tok >= 0) {
                v = emb4[(size_t)tok * 128 + kc * 16 + q];
                float m = msm[r];
                v.x *= m; v.y *= m; v.z *= m; v.w *= m;
            }
            __nv_bfloat162 h0 = __floats2bfloat162_rn(v.x, v.y);
            __nv_bfloat162 h1 = __floats2bfloat162_rn(v.z, v.w);
            uint2 pk = make_uint2(*(unsigned*)&h0, *(unsigned*)&h1);
            *(uint2*)((char*)As + r * 144 + q * 8) = pk;
        }
        for (int i = tid; i < 2304; i += 256) {
            uint4 v = w2g[kc * 2304 + i];
            int n = i >> 3, seg = i & 7;
            *(uint4*)((char*)Bs + n * 144 + seg * 16) = v;
        }
        __syncthreads();
#pragma unroll
        for (int ks = 0; ks < 4; ks++) {
            uint32_t bf[9][2];
#pragma unroll
            for (int nt = 0; nt < 9; nt++) {
                uint32_t addr = bBase + (uint32_t)(nt * 576 + ks * 16) * 2;
                asm volatile("ldmatrix.sync.aligned.m8n8.x2.shared.b16 {%0,%1}, [%2];"
                             : "=r"(bf[nt][0]), "=r"(bf[nt][1]) : "r"(addr));
            }
#pragma unroll
            for (int mt = 0; mt < 4; mt++) {
                uint32_t af[4];
                uint32_t addr = aBase + (uint32_t)(mt * 1152 + ks * 16) * 2;
                asm volatile("ldmatrix.sync.aligned.m8n8.x4.shared.b16 {%0,%1,%2,%3}, [%4];"
                             : "=r"(af[0]), "=r"(af[1]), "=r"(af[2]), "=r"(af[3]) : "r"(addr));
#pragma unroll
                for (int nt = 0; nt < 9; nt++) {
                    asm volatile(
                        "mma.sync.aligned.m16n8k16.row.col.f32.bf16.bf16.f32 "
                        "{%0,%1,%2,%3}, {%4,%5,%6,%7}, {%8,%9}, {%0,%1,%2,%3};"
                        : "+f"(acc[mt][nt][0]), "+f"(acc[mt][nt][1]),
                          "+f"(acc[mt][nt][2]), "+f"(acc[mt][nt][3])
                        : "r"(af[0]), "r"(af[1]), "r"(af[2]), "r"(af[3]),
                          "r"(bf[nt][0]), "r"(bf[nt][1]));
                }
            }
        }
    }
    __syncthreads();

    int r0 = wm * 64 + (lane >> 2);
    int c0 = wn * 72 + ((lane & 3) << 1);
#pragma unroll
    for (int mt = 0; mt < 4; mt++) {
#pragma unroll
        for (int nt = 0; nt < 9; nt++) {
            int r = r0 + mt * 16, c = c0 + nt * 8;
            *(float2*)(Ysm + r * 292 + c)       = make_float2(acc[mt][nt][0], acc[mt][nt][1]);
            *(float2*)(Ysm + (r + 8) * 292 + c) = make_float2(acc[mt][nt][2], acc[mt][nt][3]);
        }
    }
    __syncthreads();

    for (int i = tid; i < 120 * 32; i += 256) {
        int j = i >> 5, co = i & 31;
        float v = bsm[co];
#pragma unroll
        for (int t = 0; t < 9; t++) v += Ysm[(j + t) * 292 + t * 32 + co];
        int l = cx * 120 + j;
        if (l < L_) g_h[((size_t)(b * L_ + l)) * C_ + co] = fmaxf(v, 0.f);
    }
}

// ---------------- primary caps conv: 32 -> 256, k=9, pad 4, stride 2, + squash -------
__global__ void __launch_bounds__(256) k_prim(const float* __restrict__ bias) {
    __shared__ float sbuf[9504];
    int b = blockIdx.y;
    int sb = blockIdx.x * 32;
    int tid = threadIdx.x;
    int ucg = tid >> 3, sg = tid & 7;
    float acc[8][4];
#pragma unroll
    for (int i = 0; i < 8; i++)
#pragma unroll
        for (int j = 0; j < 4; j++) acc[i][j] = 0.f;

    float* hsm = sbuf;
    float* wsm = sbuf + 288;
    int lorg = 2 * sb - 4;

    for (int ch = 0; ch < 8; ch++) {
        int ci0 = ch * 4;
        __syncthreads();
        for (int row = tid; row < 72; row += 256) {
            int l = lorg + row;
            float4 v = make_float4(0.f, 0.f, 0.f, 0.f);
            if (l >= 0 && l < L_)
                v = *(const float4*)(g_h + ((size_t)(b * L_ + l)) * C_ + ci0);
            hsm[row] = v.x;
            hsm[72 + row] = v.y;
            hsm[144 + row] = v.z;
            hsm[216 + row] = v.w;
        }
        {
            const float4* src = (const float4*)(g_pwT + ci0 * 2304);
            float4* dst = (float4*)wsm;
            for (int idx = tid; idx < 2304; idx += 256) dst[idx] = src[idx];
        }
        __syncthreads();
#pragma unroll
        for (int cl = 0; cl < 4; cl++) {
            float hv[16];
            const float4* hr = (const float4*)(hsm + cl * 72 + sg * 8);
#pragma unroll
            for (int q = 0; q < 4; q++) {
                float4 v = hr[q];
                hv[q * 4 + 0] = v.x; hv[q * 4 + 1] = v.y;
                hv[q * 4 + 2] = v.z; hv[q * 4 + 3] = v.w;
            }
#pragma unroll
            for (int t = 0; t < 9; t++) {
                const float* wp = wsm + (cl * 9 + t) * 256 + ucg * 8;
                float4 wa = *(const float4*)wp;
                float4 wb = *(const float4*)(wp + 4);
                float wv[8] = {wa.x, wa.y, wa.z, wa.w, wb.x, wb.y, wb.z, wb.w};
#pragma unroll
                for (int j = 0; j < 4; j++) {
                    float h = hv[2 * j + t];
#pragma unroll
                    for (int i = 0; i < 8; i++) acc[i][j] = fmaf(wv[i], h, acc[i][j]);
                }
            }
        }
    }
    __syncthreads();
    float* psm = sbuf;
    float bi[8];
#pragma unroll
    for (int i = 0; i < 8; i++) bi[i] = bias[ucg * 8 + i];
#pragma unroll
    for (int j = 0; j < 4; j++)
#pragma unroll
        for (int i = 0; i < 8; i++)
            psm[(sg * 4 + j) * 257 + ucg * 8 + i] = acc[i][j] + bi[i];
    __syncthreads();
    int u = tid >> 5, sl = tid & 31;
    const float* pr = psm + sl * 257 + u * 32;
    float sq = 0.f;
#pragma unroll
    for (int c = 0; c < 32; c++) { float pv = pr[c]; sq += pv * pv; }
    float sc = (sq / (1.f + sq)) * rsqrtf(sq + 1e-8f);
    float* dst = g_p + (((size_t)(b * U_ + u)) * S_ + sb + sl) * C_;
#pragma unroll
    for (int c = 0; c < 32; c++) dst[c] = pr[c] * sc;
}

// ---------------- u_hat via tf32 HMMA: Y[256,288] = p[256,32] @ Wpack[288,32]^T ------
// Grid (U, B), 256 threads (8 warps: 4M x 2N), N in 3 groups of 96.
// Fragments gathered by scalar LDS (stride-36 rows: conflict-free), cvt.rna.tf32.
// Output written directly into [b,u,k][cp][s] bf16x2 layout (mapping validated R12).
__global__ void __launch_bounds__(256) k_uhat(const float* __restrict__ Wunused) {
    extern __shared__ float uhsm[];
    float* Ap = uhsm;            // [256][36]
    float* Wp = uhsm + 256 * 36; // [288][36]
    int u = blockIdx.x, b = blockIdx.y;
    int tid = threadIdx.x, lane = tid & 31, w = tid >> 5;
    int wm = w >> 1, wn = w & 1;

    // stage A: p fp32 (coalesced float4 read, scalar scatter)
    const float4* p4 = (const float4*)(g_p + ((size_t)(b * U_ + u)) * S_ * C_);
    for (int i = tid; i < 2048; i += 256) {
        float4 v = p4[i];
        float* d = Ap + (i >> 3) * 36 + (i & 7) * 4;
        d[0] = v.x; d[1] = v.y; d[2] = v.z; d[3] = v.w;
    }
    // stage B: Wpack[u] 288x32 fp32
    const float4* wp4 = (const float4*)g_wp + (size_t)u * 2304;
    for (int i = tid; i < 2304; i += 256) {
        float4 v = wp4[i];
        float* d = Wp + (i >> 3) * 36 + (i & 7) * 4;
        d[0] = v.x; d[1] = v.y; d[2] = v.z; d[3] = v.w;
    }
    __syncthreads();

    int gid = lane >> 2, tig = lane & 3;
    unsigned* uhb = (unsigned*)g_uh;

#pragma unroll 1
    for (int ngrp = 0; ngrp < 3; ngrp++) {
        float acc[4][6][4];
#pragma unroll
        for (int mt = 0; mt < 4; mt++)
#pragma unroll
            for (int nt = 0; nt < 6; nt++)
#pragma unroll
                for (int j = 0; j < 4; j++) acc[mt][nt][j] = 0.f;
#pragma unroll
        for (int ks = 0; ks < 4; ks++) {
            int kb = ks * 8;
            uint32_t af[4][4];
#pragma unroll
            for (int mt = 0; mt < 4; mt++) {
                const float* ar = Ap + (wm * 64 + mt * 16 + gid) * 36 + kb + tig;
                af[mt][0] = f2tf32(ar[0]);
                af[mt][1] = f2tf32(ar[8 * 36]);
                af[mt][2] = f2tf32(ar[4]);
                af[mt][3] = f2tf32(ar[8 * 36 + 4]);
            }
            uint32_t bf[6][2];
#pragma unroll
            for (int nt = 0; nt < 6; nt++) {
                const float* br = Wp + (ngrp * 96 + wn * 48 + nt * 8 + gid) * 36 + kb + tig;
                bf[nt][0] = f2tf32(br[0]);
                bf[nt][1] = f2tf32(br[4]);
            }
#pragma unroll
            for (int mt = 0; mt < 4; mt++)
#pragma unroll
                for (int nt = 0; nt < 6; nt++) {
                    asm volatile(
                        "mma.sync.aligned.m16n8k8.row.col.f32.tf32.tf32.f32 "
                        "{%0,%1,%2,%3}, {%4,%5,%6,%7}, {%8,%9}, {%0,%1,%2,%3};"
                        : "+f"(acc[mt][nt][0]), "+f"(acc[mt][nt][1]),
                          "+f"(acc[mt][nt][2]), "+f"(acc[mt][nt][3])
                        : "r"(af[mt][0]), "r"(af[mt][1]), "r"(af[mt][2]), "r"(af[mt][3]),
                          "r"(bf[nt][0]), "r"(bf[nt][1]));
                }
        }
        // store fragments into [b,u,kk][cp][s] bf16x2 (validated mapping)
#pragma unroll
        for (int mt = 0; mt < 4; mt++) {
            int srow = wm * 64 + mt * 16 + gid;
#pragma unroll
            for (int nt = 0; nt < 6; nt++) {
                int ncol = ngrp * 96 + wn * 48 + nt * 8;
                int kk = ncol >> 5;
                int cp = ((ncol & 31) >> 1) + tig;
                size_t ubase = ((size_t)((b * U_ + u) * K_ + kk)) * 4096;
                __nv_bfloat162 w0 = __floats2bfloat162_rn(acc[mt][nt][0], acc[mt][nt][1]);
                __nv_bfloat162 w1 = __floats2bfloat162_rn(acc[mt][nt][2], acc[mt][nt][3]);
                uhb[ubase + cp * 256 + srow]     = *(unsigned*)&w0;
                uhb[ubase + cp * 256 + srow + 8] = *(unsigned*)&w1;
            }
        }
    }
}

// ---------------- routing iteration (u_hat bf16, [b,u,k][cp][s] layout) ------------
template <int PHASE>
__global__ void __launch_bounds__(256) k_route(float* __restrict__ out) {
    __shared__ float cs[8];
    __shared__ float sbuf[8448];
    int k = blockIdx.x, b = blockIdx.y, s = threadIdx.x;

    if (PHASE == 0) {
        if (s < 8) cs[s] = 1.f / 9.f;
    } else {
        const float* lin = (PHASE == 1) ? g_logA : g_logB;
        if (s < 8) {
            const float* lp = lin + (b * U_ + s) * K_;
            float lg[9], m = -1e30f;
#pragma unroll
            for (int i = 0; i < 9; i++) { lg[i] = lp[i]; m = fmaxf(m, lg[i]); }
            float sum = 0.f;
#pragma unroll
            for (int i = 0; i < 9; i++) sum += expf(lg[i] - m);
            cs[s] = expf(lg[k] - m) / sum;
        }
    }
    __syncthreads();

    const unsigned* uhb = (const unsigned*)g_uh;
    float sa[32];
#pragma unroll
    for (int c = 0; c < 32; c++) sa[c] = 0.f;
#pragma unroll 1
    for (int u = 0; u < 8; u++) {
        float cu = cs[u];
        const unsigned* base = uhb + ((size_t)((b * U_ + u) * K_ + k)) * 4096 + s;
#pragma unroll
        for (int cp = 0; cp < 16; cp++) {
            unsigned r = base[cp * 256];
            float2 t = __bfloat1622float2(*(__nv_bfloat162*)&r);
            sa[2 * cp]     = fmaf(cu, t.x, sa[2 * cp]);
            sa[2 * cp + 1] = fmaf(cu, t.y, sa[2 * cp + 1]);
        }
    }
    float sq = 0.f;
#pragma unroll
    for (int c = 0; c < 32; c++) sq += sa[c] * sa[c];
    float sc = (sq / (1.f + sq)) * rsqrtf(sq + 1e-8f);
    float v8[32];
#pragma unroll
    for (int c = 0; c < 32; c++) v8[c] = sa[c] * sc;

    if (PHASE < 2) {
#pragma unroll 1
        for (int u = 0; u < 8; u++) {
            const unsigned* base = uhb + ((size_t)((b * U_ + u) * K_ + k)) * 4096 + s;
            float d = 0.f;
#pragma unroll
            for (int cp = 0; cp < 16; cp++) {
                unsigned r = base[cp * 256];
                float2 t = __bfloat1622float2(*(__nv_bfloat162*)&r);
                d = fmaf(t.x, v8[2 * cp], d);
                d = fmaf(t.y, v8[2 * cp + 1], d);
            }
            sbuf[u * 256 + s] = d;
        }
        __syncthreads();
        int warp = s >> 5, lane = s & 31;
        float t = 0.f;
#pragma unroll
        for (int j = 0; j < 8; j++) t += sbuf[warp * 256 + lane + j * 32];
#pragma unroll
        for (int off = 16; off > 0; off >>= 1) t += __shfl_xor_sync(0xffffffffu, t, off);
        if (lane == 0) {
            int li = (b * U_ + warp) * K_ + k;
            if (PHASE == 0) g_logA[li] = t;
            else            g_logB[li] = g_logA[li] + t;
        }
    } else {
#pragma unroll
        for (int c = 0; c < 32; c++) sbuf[s * 33 + c] = v8[c];
        __syncthreads();
        int col = s & 31, seg = s >> 5;
        float t = 0.f;
#pragma unroll
        for (int r = 0; r < 32; r++) t += sbuf[(seg * 32 + r) * 33 + col];
        __syncthreads();
        sbuf[seg * 32 + col] = t;
        __syncthreads();
        if (s < 32) {
            float acc = 0.f;
#pragma unroll
            for (int g = 0; g < 8; g++) acc += sbuf[g * 32 + s];
            out[(b * K_ + k) * C_ + s] = acc * (1.f / 256.f);
        }
    }
}

// ---------------- launch ----------------
extern "C" void kernel_launch(void* const* d_in, const int* in_sizes, int n_in,
                              void* d_out, int out_size) {
    const int*   x    = (const int*)d_in[0];
    const float* mask = (const float*)d_in[1];
    const float* emb  = (const float*)d_in[2];
    const float* c1w  = (const float*)d_in[3];
    const float* c1b  = (const float*)d_in[4];
    const float* pw   = (const float*)d_in[5];
    const float* pb   = (const float*)d_in[6];
    const float* W    = (const float*)d_in[7];
    float* out = (float*)d_out;

    const int CONV_SMEM = 210560;
    const int UHAT_SMEM = (256 * 36 + 288 * 36) * 4;  // 78336
    static int attr_set = 0;
    if (!attr_set) {
        cudaFuncSetAttribute(k_conv1_mma, cudaFuncAttributeMaxDynamicSharedMemorySize, CONV_SMEM);
        cudaFuncSetAttribute(k_uhat, cudaFuncAttributeMaxDynamicSharedMemorySize, UHAT_SMEM);
        attr_set = 1;
    }

    int prep_elems = 288 * 512 + C_ * 9 * 256 + U_ * 288 * 32;
    k_prep<<<(prep_elems + 255) / 256, 256>>>(c1w, pw, W);
    k_conv1_mma<<<dim3(5, B_), 256, CONV_SMEM>>>(x, mask, emb, c1b);
    k_prim<<<dim3(S_ / 32, B_), 256>>>(pb);
    k_uhat<<<dim3(U_, B_), 256, UHAT_SMEM>>>(W);
    k_route<0><<<dim3(K_, B_), 256>>>(out);
    k_route<1><<<dim3(K_, B_), 256>>>(out);
    k_route<2><<<dim3(K_, B_), 256>>>(out);
}